// round 2
// baseline (speedup 1.0000x reference)
#include <cuda_runtime.h>

#define NN   20000
#define FF   4
#define TT   12
#define CC   256
#define HIDN 128
#define OUTN 12
#define ERN  30000
#define NREG 5
#define FT   48   // F*T floats per node

struct RegPtrs { const int* ei[NREG]; const float* ew[NREG]; };

// Scratch (no allocations allowed)
__device__ float g_deg [NREG * NN];
__device__ float g_dinv[NREG * NN];
__device__ float g_y   [NN * FT];        // aggregated x: [N, F, T]
__device__ float g_M   [2 * FF * CC];    // composite Wc@Wl[:C] for z (0) and h (1)
__device__ float g_bias[2 * CC];         // composite bc@Wl[:C] + bl
__device__ float g_p   [TT];             // softmax(attention)
__device__ float g_h   [NN * CC];        // pooled hidden state

// ---------------------------------------------------------------- deg init
__global__ void k_init_deg() {
    int i = blockIdx.x * blockDim.x + threadIdx.x;
    if (i < NREG * NN) g_deg[i] = 1.0f;   // +1 from self-loop
}

// ------------------------------------------------------------- deg scatter
__global__ void k_deg(RegPtrs rp) {
    int i = blockIdx.x * blockDim.x + threadIdx.x;
    if (i >= NREG * ERN) return;
    int r = i / ERN;
    int e = i - r * ERN;
    int dst = rp.ei[r][ERN + e];          // edge_index row 1
    atomicAdd(&g_deg[r * NN + dst], rp.ew[r][e]);
}

// ---------------------------------------------------------------- dinv
__global__ void k_dinv() {
    int i = blockIdx.x * blockDim.x + threadIdx.x;
    if (i < NREG * NN) g_dinv[i] = rsqrtf(g_deg[i]);
}

// ---------------------------------------------- y = (sum_r dinv_r^2) * x
__global__ void k_y0(const float* __restrict__ x) {
    int i = blockIdx.x * blockDim.x + threadIdx.x;   // one float4 (4 of 48 floats)
    if (i >= NN * TT) return;
    int n = i / TT;
    float S = 0.0f;
#pragma unroll
    for (int r = 0; r < NREG; r++) {
        float d = g_dinv[r * NN + n];
        S += d * d;
    }
    float4 v = reinterpret_cast<const float4*>(x)[i];
    v.x *= S; v.y *= S; v.z *= S; v.w *= S;
    reinterpret_cast<float4*>(g_y)[i] = v;
}

// --------------------------------------- message scatter: y[dst] += coef*x[src]
__global__ void k_msg(const float* __restrict__ x, RegPtrs rp) {
    int i = blockIdx.x * blockDim.x + threadIdx.x;   // (edge, chunk-of-4)
    if (i >= NREG * ERN * TT) return;
    int chunk = i % TT;
    int eg    = i / TT;
    int r     = eg / ERN;
    int e     = eg - r * ERN;
    int src = rp.ei[r][e];
    int dst = rp.ei[r][ERN + e];
    float w = rp.ew[r][e];
    float coef = g_dinv[r * NN + src] * w * g_dinv[r * NN + dst];
    float4 v = reinterpret_cast<const float4*>(x)[src * TT + chunk];
    float* yp = g_y + dst * FT + chunk * 4;
    atomicAdd(yp + 0, coef * v.x);
    atomicAdd(yp + 1, coef * v.y);
    atomicAdd(yp + 2, coef * v.z);
    atomicAdd(yp + 3, coef * v.w);
}

// -------------------------- composite weights M = Wc @ Wl[:C], b' = bc@Wl + bl
__global__ void k_weights(const float* __restrict__ Wc_z, const float* __restrict__ bc_z,
                          const float* __restrict__ Wl_z, const float* __restrict__ bl_z,
                          const float* __restrict__ Wc_h, const float* __restrict__ bc_h,
                          const float* __restrict__ Wl_h, const float* __restrict__ bl_h,
                          const float* __restrict__ att) {
    int t = threadIdx.x;                  // 0..511
    int g = t >> 8;                       // 0 = z, 1 = h
    int c = t & (CC - 1);
    const float* Wc = g ? Wc_h : Wc_z;
    const float* bc = g ? bc_h : bc_z;
    const float* Wl = g ? Wl_h : Wl_z;
    const float* bl = g ? bl_h : bl_z;
    float a0 = 0, a1 = 0, a2 = 0, a3 = 0, ab = 0;
    for (int k = 0; k < CC; k++) {
        float wl = Wl[k * CC + c];        // first C rows of [2C, C]
        a0 += Wc[0 * CC + k] * wl;
        a1 += Wc[1 * CC + k] * wl;
        a2 += Wc[2 * CC + k] * wl;
        a3 += Wc[3 * CC + k] * wl;
        ab += bc[k] * wl;
    }
    g_M[g * FF * CC + 0 * CC + c] = a0;
    g_M[g * FF * CC + 1 * CC + c] = a1;
    g_M[g * FF * CC + 2 * CC + c] = a2;
    g_M[g * FF * CC + 3 * CC + c] = a3;
    g_bias[g * CC + c] = ab + bl[c];
    if (t == 0) {                          // softmax(attention), T=12
        float m = -1e30f;
        for (int k = 0; k < TT; k++) m = fmaxf(m, att[k]);
        float s = 0.0f;
        float e[TT];
        for (int k = 0; k < TT; k++) { e[k] = __expf(att[k] - m); s += e[k]; }
        float inv = 1.0f / s;
        for (int k = 0; k < TT; k++) g_p[k] = e[k] * inv;
    }
}

// ------------------- fused gates + attention pooling: h[n,c] = sum_t p_t*(1-Z)*tanh
__global__ void k_gate() {
    __shared__ float ys[FT];
    __shared__ float ps[TT];
    int n = blockIdx.x;
    int c = threadIdx.x;
    if (c < 12) reinterpret_cast<float4*>(ys)[c] =
        reinterpret_cast<const float4*>(g_y + n * FT)[c];
    if (c >= 32 && c < 32 + TT) ps[c - 32] = g_p[c - 32];
    __syncthreads();

    float mz0 = g_M[0 * CC + c], mz1 = g_M[1 * CC + c];
    float mz2 = g_M[2 * CC + c], mz3 = g_M[3 * CC + c];
    float mh0 = g_M[4 * CC + c], mh1 = g_M[5 * CC + c];
    float mh2 = g_M[6 * CC + c], mh3 = g_M[7 * CC + c];
    float bz = g_bias[c], bh = g_bias[CC + c];

    float h = 0.0f;
#pragma unroll
    for (int t = 0; t < TT; t++) {
        float y0 = ys[t], y1 = ys[TT + t], y2 = ys[2 * TT + t], y3 = ys[3 * TT + t];
        float az = bz + mz0 * y0 + mz1 * y1 + mz2 * y2 + mz3 * y3;
        float ah = bh + mh0 * y0 + mh1 * y1 + mh2 * y2 + mh3 * y3;
        az = fminf(fmaxf(az, -30.0f), 30.0f);
        ah = fminf(fmaxf(ah, -15.0f), 15.0f);
        float ez = __expf(-az);            // (1-sigmoid(az)) = ez/(1+ez)
        float eh = __expf(2.0f * ah);      // tanh(ah) = (eh-1)/(eh+1)
        float num = ez * (eh - 1.0f);
        float den = (1.0f + ez) * (eh + 1.0f);
        h += ps[t] * __fdividef(num, den); // one rcp for both factors
    }
    g_h[n * CC + c] = h;
}

// ---------------------------------------------------------------- copy h out
__global__ void k_copyh(float* __restrict__ dst) {
    int i = blockIdx.x * blockDim.x + threadIdx.x;
    if (i < NN * CC / 4)
        reinterpret_cast<float4*>(dst)[i] = reinterpret_cast<const float4*>(g_h)[i];
}

// ------------------------------------- MLP: y = relu(relu(h)@W1+b1)@W2+b2
// 32 nodes per block, 2 groups x 128 hid-threads, 16-node register blocking.
__global__ void __launch_bounds__(256) k_mlp(const float* __restrict__ W1,
                                             const float* __restrict__ b1,
                                             const float* __restrict__ W2,
                                             const float* __restrict__ b2,
                                             float* __restrict__ yout) {
    __shared__ float hs[32 * CC];    // 32 KB: relu(h) tile
    __shared__ float s1[32 * HIDN];  // 16 KB: hidden activations
    int tid = threadIdx.x;
    int node0 = blockIdx.x * 32;

    // load + relu 32 nodes of h (8192 floats = 2048 float4)
    for (int i = tid; i < 32 * CC / 4; i += 256) {
        float4 v = reinterpret_cast<const float4*>(g_h + node0 * CC)[i];
        v.x = fmaxf(v.x, 0.0f); v.y = fmaxf(v.y, 0.0f);
        v.z = fmaxf(v.z, 0.0f); v.w = fmaxf(v.w, 0.0f);
        reinterpret_cast<float4*>(hs)[i] = v;
    }
    __syncthreads();

    int g   = tid >> 7;        // node-group 0/1 (16 nodes each)
    int hid = tid & (HIDN - 1);
    int nb  = g * 16;

    float acc[16];
    float bias1 = b1[hid];
#pragma unroll
    for (int nn = 0; nn < 16; nn++) acc[nn] = bias1;

    for (int cidx = 0; cidx < CC; cidx++) {
        float w = W1[cidx * HIDN + hid];
#pragma unroll
        for (int nn = 0; nn < 16; nn++)
            acc[nn] += hs[(nb + nn) * CC + cidx] * w;   // LDS broadcast
    }
#pragma unroll
    for (int nn = 0; nn < 16; nn++)
        s1[(nb + nn) * HIDN + hid] = fmaxf(acc[nn], 0.0f);
    __syncthreads();

    // second layer: 32 nodes x 12 outputs
    for (int o = tid; o < 32 * OUTN; o += 256) {
        int node = o / OUTN;
        int oo   = o - node * OUTN;
        float a = b2[oo];
#pragma unroll
        for (int k = 0; k < HIDN; k++)
            a += s1[node * HIDN + k] * W2[k * OUTN + oo];
        yout[(node0 + node) * OUTN + oo] = a;
    }
}

// ================================================================== host
extern "C" void kernel_launch(void* const* d_in, const int* in_sizes, int n_in,
                              void* d_out, int out_size) {
    const float* x = (const float*)d_in[0];
    RegPtrs rp;
    for (int r = 0; r < NREG; r++) {
        rp.ei[r] = (const int*)d_in[2 + r];     // IA,KS,KY,OH,WI edge_index
        rp.ew[r] = (const float*)d_in[7 + r];   // matching edge_attr
    }
    const float* Wc_z = (const float*)d_in[12];
    const float* bc_z = (const float*)d_in[13];
    const float* Wl_z = (const float*)d_in[14];
    const float* bl_z = (const float*)d_in[15];
    const float* Wc_h = (const float*)d_in[20];
    const float* bc_h = (const float*)d_in[21];
    const float* Wl_h = (const float*)d_in[22];
    const float* bl_h = (const float*)d_in[23];
    const float* att  = (const float*)d_in[24];
    const float* W1   = (const float*)d_in[25];
    const float* b1   = (const float*)d_in[26];
    const float* W2   = (const float*)d_in[27];
    const float* b2   = (const float*)d_in[28];

    float* out  = (float*)d_out;
    float* ydst = nullptr;
    float* hdst = nullptr;
    if (out_size >= NN * OUTN + NN * CC) { ydst = out; hdst = out + NN * OUTN; }
    else if (out_size >= NN * CC)        { hdst = out; }
    else                                 { ydst = out; }

    k_init_deg<<<(NREG * NN + 255) / 256, 256>>>();
    k_deg<<<(NREG * ERN + 255) / 256, 256>>>(rp);
    k_dinv<<<(NREG * NN + 255) / 256, 256>>>();
    k_y0<<<(NN * TT + 255) / 256, 256>>>(x);
    k_msg<<<(NREG * ERN * TT + 255) / 256, 256>>>(x, rp);
    k_weights<<<1, 512>>>(Wc_z, bc_z, Wl_z, bl_z, Wc_h, bc_h, Wl_h, bl_h, att);
    k_gate<<<NN, 256>>>();
    if (hdst) k_copyh<<<(NN * CC / 4 + 255) / 256, 256>>>(hdst);
    if (ydst) k_mlp<<<NN / 32, 256>>>(W1, b1, W2, b2, ydst);
}

// round 4
// speedup vs baseline: 1.4531x; 1.4531x over previous
#include <cuda_runtime.h>

#define NN   20000
#define FF   4
#define TT   12
#define CC   256
#define HIDN 128
#define OUTN 12
#define ERN  30000
#define NREG 5
#define FT   48   // F*T floats per node

typedef unsigned long long u64;

struct RegPtrs { const int* ei[NREG]; const float* ew[NREG]; };

// ---------------------------------------------------------------- f32x2 / tanh helpers
__device__ __forceinline__ u64 pack2(float lo, float hi) {
    u64 r; asm("mov.b64 %0,{%1,%2};" : "=l"(r) : "f"(lo), "f"(hi)); return r;
}
__device__ __forceinline__ void unpack2(u64 v, float& lo, float& hi) {
    asm("mov.b64 {%0,%1},%2;" : "=f"(lo), "=f"(hi) : "l"(v));
}
__device__ __forceinline__ u64 ffma2(u64 a, u64 b, u64 c) {
    u64 d; asm("fma.rn.f32x2 %0,%1,%2,%3;" : "=l"(d) : "l"(a), "l"(b), "l"(c)); return d;
}
__device__ __forceinline__ float tanh_fast(float x) {
    float r; asm("tanh.approx.f32 %0,%1;" : "=f"(r) : "f"(x)); return r;
}

// ---------------------------------------------------------------- scratch
__device__ float g_deg[NREG * NN];
__device__ float g_y  [NN * FT];       // aggregated x: [N, F, T]
__device__ u64   g_M2 [FF * CC];       // pairs (0.5*Mz, Mh) per (f, c)
__device__ u64   g_b2 [CC];            // pairs (0.5*bz', bh')
__device__ float g_ph [TT];            // 0.5 * softmax(attention)
__device__ float g_h  [NN * CC];       // fallback h buffer

// ------------------------- K1: deg init + composite weights + softmax (block 0)
__global__ void k_init_w(const float* __restrict__ Wc_z, const float* __restrict__ bc_z,
                         const float* __restrict__ Wl_z, const float* __restrict__ bl_z,
                         const float* __restrict__ Wc_h, const float* __restrict__ bc_h,
                         const float* __restrict__ Wl_h, const float* __restrict__ bl_h,
                         const float* __restrict__ att) {
    if (blockIdx.x == 0) {
        int t = threadIdx.x;              // 0..511
        int g = t >> 8;                   // 0 = z, 1 = h
        int c = t & (CC - 1);
        const float* Wc = g ? Wc_h : Wc_z;
        const float* bc = g ? bc_h : bc_z;
        const float* Wl = g ? Wl_h : Wl_z;
        const float* bl = g ? bl_h : bl_z;
        float a0 = 0, a1 = 0, a2 = 0, a3 = 0, ab = 0;
        for (int k = 0; k < CC; k++) {
            float wl = Wl[k * CC + c];    // first C rows of [2C, C]
            a0 += Wc[0 * CC + k] * wl;
            a1 += Wc[1 * CC + k] * wl;
            a2 += Wc[2 * CC + k] * wl;
            a3 += Wc[3 * CC + k] * wl;
            ab += bc[k] * wl;
        }
        float s = g ? 1.0f : 0.5f;        // fold tanh half-angle into z weights
        float* M = (float*)g_M2;
        M[(0 * CC + c) * 2 + g] = a0 * s;
        M[(1 * CC + c) * 2 + g] = a1 * s;
        M[(2 * CC + c) * 2 + g] = a2 * s;
        M[(3 * CC + c) * 2 + g] = a3 * s;
        ((float*)g_b2)[c * 2 + g] = (ab + bl[c]) * s;
        if (t == 0) {                     // 0.5 * softmax(attention)
            float m = -1e30f;
            for (int k = 0; k < TT; k++) m = fmaxf(m, att[k]);
            float sum = 0.0f, e[TT];
            for (int k = 0; k < TT; k++) { e[k] = __expf(att[k] - m); sum += e[k]; }
            float inv = 0.5f / sum;
            for (int k = 0; k < TT; k++) g_ph[k] = e[k] * inv;
        }
    } else {
        int i = (blockIdx.x - 1) * blockDim.x + threadIdx.x;
        if (i < NREG * NN) g_deg[i] = 1.0f;   // +1 from self-loop
    }
}

// ------------------------------------------------------------- K2: deg scatter
__global__ void k_deg(RegPtrs rp) {
    int i = blockIdx.x * blockDim.x + threadIdx.x;
    if (i >= NREG * ERN) return;
    int r = i / ERN;
    int e = i - r * ERN;
    int dst = rp.ei[r][ERN + e];
    atomicAdd(&g_deg[r * NN + dst], rp.ew[r][e]);
}

// --------------------------------------------- K3: y = (sum_r dinv_r^2) * x
__global__ void k_y0(const float* __restrict__ x) {
    int i = blockIdx.x * blockDim.x + threadIdx.x;   // one float4 chunk
    if (i >= NN * TT) return;
    int n = i / TT;
    float S = 0.0f;
#pragma unroll
    for (int r = 0; r < NREG; r++) {
        float d = rsqrtf(g_deg[r * NN + n]);
        S += d * d;
    }
    float4 v = reinterpret_cast<const float4*>(x)[i];
    v.x *= S; v.y *= S; v.z *= S; v.w *= S;
    reinterpret_cast<float4*>(g_y)[i] = v;
}

// ------------------------------- K4: message scatter: y[dst] += coef * x[src]
__global__ void k_msg(const float* __restrict__ x, RegPtrs rp) {
    int i = blockIdx.x * blockDim.x + threadIdx.x;   // one edge
    if (i >= NREG * ERN) return;
    int r = i / ERN;
    int e = i - r * ERN;
    int src = rp.ei[r][e];
    int dst = rp.ei[r][ERN + e];
    float w = rp.ew[r][e];
    float coef = rsqrtf(g_deg[r * NN + src]) * w * rsqrtf(g_deg[r * NN + dst]);
    const float4* xs = reinterpret_cast<const float4*>(x) + src * TT;
    float* yp = g_y + dst * FT;
#pragma unroll
    for (int ch = 0; ch < TT; ch++) {
        float4 v = xs[ch];
        atomicAdd(yp + ch * 4 + 0, coef * v.x);
        atomicAdd(yp + ch * 4 + 1, coef * v.y);
        atomicAdd(yp + ch * 4 + 2, coef * v.z);
        atomicAdd(yp + ch * 4 + 3, coef * v.w);
    }
}

// ------------------- K5: fused gates + attention pooling (tanh-HW, f32x2 FFMA)
// h[n,c] = sum_t (0.5 p_t) * (1 - tanh(az/2)) * tanh(ah)
__global__ void __launch_bounds__(256) k_gate(float* __restrict__ hout) {
    __shared__ u64   yp[TT * FF];   // [t][f] duplicated pairs (y, y)
    __shared__ float ph[TT];
    int n = blockIdx.x;
    int c = threadIdx.x;
    if (c < FT) {
        int t = c >> 2, f = c & 3;
        float v = g_y[n * FT + f * TT + t];
        yp[t * 4 + f] = pack2(v, v);
    }
    if (c >= 64 && c < 64 + TT) ph[c - 64] = g_ph[c - 64];
    __syncthreads();

    u64 m0 = g_M2[0 * CC + c], m1 = g_M2[1 * CC + c];
    u64 m2 = g_M2[2 * CC + c], m3 = g_M2[3 * CC + c];
    u64 b  = g_b2[c];

    float h = 0.0f;
#pragma unroll
    for (int t = 0; t < TT; t++) {
        u64 a = ffma2(yp[t * 4 + 0], m0, b);
        a = ffma2(yp[t * 4 + 1], m1, a);
        a = ffma2(yp[t * 4 + 2], m2, a);
        a = ffma2(yp[t * 4 + 3], m3, a);
        float azh, ahh;
        unpack2(a, azh, ahh);                 // lo = 0.5*az, hi = ah
        float tz = tanh_fast(azh);
        float th = tanh_fast(ahh);
        h = fmaf(ph[t] * (1.0f - tz), th, h);
    }
    hout[n * CC + c] = h;
}

// ------------------- K6: MLP y = relu(relu(h)@W1+b1)@W2+b2, f32x2 over C pairs
__global__ void __launch_bounds__(256) k_mlp(const float* __restrict__ h_src,
                                             const float* __restrict__ W1,
                                             const float* __restrict__ b1,
                                             const float* __restrict__ W2,
                                             const float* __restrict__ b2,
                                             float* __restrict__ yout) {
    __shared__ float hs[32 * CC];        // 32 KB: relu(h) tile [node][c]
    __shared__ float w2s[HIDN * OUTN];   // 6 KB
    float* s1 = hs;                      // aliased after layer 1 (16 KB)

    int tid = threadIdx.x;
    int node0 = blockIdx.x * 32;

    for (int i = tid; i < HIDN * OUTN; i += 256) w2s[i] = W2[i];

    // load + relu 32 nodes of h
    for (int i = tid; i < 32 * CC / 4; i += 256) {
        float4 v = reinterpret_cast<const float4*>(h_src + (size_t)node0 * CC)[i];
        v.x = fmaxf(v.x, 0.0f); v.y = fmaxf(v.y, 0.0f);
        v.z = fmaxf(v.z, 0.0f); v.w = fmaxf(v.w, 0.0f);
        reinterpret_cast<float4*>(hs)[i] = v;
    }
    __syncthreads();

    int g   = tid >> 7;                  // node-group 0/1 (16 nodes each)
    int hid = tid & (HIDN - 1);
    const float* hsg = hs + g * 16 * CC;

    u64 acc[16];
#pragma unroll
    for (int nn = 0; nn < 16; nn++) acc[nn] = 0ull;

#pragma unroll 2
    for (int k4 = 0; k4 < CC; k4 += 4) {
        float w0 = W1[(k4 + 0) * HIDN + hid];
        float w1 = W1[(k4 + 1) * HIDN + hid];
        float w2 = W1[(k4 + 2) * HIDN + hid];
        float w3 = W1[(k4 + 3) * HIDN + hid];
        u64 wp0 = pack2(w0, w1);
        u64 wp1 = pack2(w2, w3);
#pragma unroll
        for (int nn = 0; nn < 16; nn++) {
            ulonglong2 hv = *reinterpret_cast<const ulonglong2*>(hsg + nn * CC + k4);
            acc[nn] = ffma2(hv.x, wp0, acc[nn]);
            acc[nn] = ffma2(hv.y, wp1, acc[nn]);
        }
    }

    float bias1 = b1[hid];
    float res[16];
#pragma unroll
    for (int nn = 0; nn < 16; nn++) {
        float lo, hi;
        unpack2(acc[nn], lo, hi);
        res[nn] = fmaxf(lo + hi + bias1, 0.0f);
    }
    __syncthreads();                      // all hs reads done before aliasing
#pragma unroll
    for (int nn = 0; nn < 16; nn++)
        s1[(g * 16 + nn) * HIDN + hid] = res[nn];
    __syncthreads();

    // layer 2: 32 nodes x 12 outputs
    for (int o = tid; o < 32 * OUTN; o += 256) {
        int node = o / OUTN;
        int oo   = o - node * OUTN;
        float a = b2[oo];
#pragma unroll 4
        for (int k = 0; k < HIDN; k++)
            a = fmaf(s1[node * HIDN + k], w2s[k * OUTN + oo], a);
        yout[(node0 + node) * OUTN + oo] = a;
    }
}

// ================================================================== host
extern "C" void kernel_launch(void* const* d_in, const int* in_sizes, int n_in,
                              void* d_out, int out_size) {
    const float* x = (const float*)d_in[0];
    RegPtrs rp;
    for (int r = 0; r < NREG; r++) {
        rp.ei[r] = (const int*)d_in[2 + r];     // IA,KS,KY,OH,WI edge_index
        rp.ew[r] = (const float*)d_in[7 + r];   // matching edge_attr
    }
    const float* Wc_z = (const float*)d_in[12];
    const float* bc_z = (const float*)d_in[13];
    const float* Wl_z = (const float*)d_in[14];
    const float* bl_z = (const float*)d_in[15];
    const float* Wc_h = (const float*)d_in[20];
    const float* bc_h = (const float*)d_in[21];
    const float* Wl_h = (const float*)d_in[22];
    const float* bl_h = (const float*)d_in[23];
    const float* att  = (const float*)d_in[24];
    const float* W1   = (const float*)d_in[25];
    const float* b1   = (const float*)d_in[26];
    const float* W2   = (const float*)d_in[27];
    const float* b2   = (const float*)d_in[28];

    float* out  = (float*)d_out;
    float* ydst = nullptr;
    float* hdst = nullptr;
    if (out_size >= NN * OUTN + NN * CC) { ydst = out; hdst = out + NN * OUTN; }
    else if (out_size >= NN * CC)        { hdst = out; }
    else                                 { ydst = out; }

    float* hbuf = hdst ? hdst : g_h;   // device-symbol address valid on device only
    // NOTE: g_h is a __device__ symbol; taking its address on host is invalid.
    // Resolve it properly:
    if (!hdst) {
        void* p = nullptr;
        cudaGetSymbolAddress(&p, g_h);
        hbuf = (float*)p;
    }

    k_init_w<<<1 + (NREG * NN + 511) / 512, 512>>>(Wc_z, bc_z, Wl_z, bl_z,
                                                   Wc_h, bc_h, Wl_h, bl_h, att);
    k_deg<<<(NREG * ERN + 255) / 256, 256>>>(rp);
    k_y0<<<(NN * TT + 255) / 256, 256>>>(x);
    k_msg<<<(NREG * ERN + 255) / 256, 256>>>(x, rp);
    k_gate<<<NN, 256>>>(hbuf);
    if (ydst) k_mlp<<<NN / 32, 256>>>(hbuf, W1, b1, W2, b2, ydst);
}

// round 6
// speedup vs baseline: 1.6842x; 1.1590x over previous
#include <cuda_runtime.h>

#define NN   20000
#define FF   4
#define TT   12
#define CC   256
#define HIDN 128
#define OUTN 12
#define ERN  30000
#define NREG 5
#define FT   48   // F*T floats per node

typedef unsigned long long u64;

struct RegPtrs { const int* ei[NREG]; const float* ew[NREG]; };

// ---------------------------------------------------------------- helpers
__device__ __forceinline__ u64 pack2(float lo, float hi) {
    u64 r; asm("mov.b64 %0,{%1,%2};" : "=l"(r) : "f"(lo), "f"(hi)); return r;
}
__device__ __forceinline__ void unpack2(u64 v, float& lo, float& hi) {
    asm("mov.b64 {%0,%1},%2;" : "=f"(lo), "=f"(hi) : "l"(v));
}
__device__ __forceinline__ u64 ffma2(u64 a, u64 b, u64 c) {
    u64 d; asm("fma.rn.f32x2 %0,%1,%2,%3;" : "=l"(d) : "l"(a), "l"(b), "l"(c)); return d;
}
__device__ __forceinline__ float tanh_fast(float x) {
    float r; asm("tanh.approx.f32 %0,%1;" : "=f"(r) : "f"(x)); return r;
}
__device__ __forceinline__ void red4(float4* p, float a, float b, float c, float d) {
    asm volatile("red.global.add.v4.f32 [%0], {%1,%2,%3,%4};"
                 :: "l"(p), "f"(a), "f"(b), "f"(c), "f"(d) : "memory");
}

// ---------------------------------------------------------------- scratch
__device__ float g_deg[NREG * NN];
__device__ __align__(16) float g_y[NN * FT];   // message accumulator [N, F, T]
__device__ u64   g_M2 [FF * CC];   // pairs (0.5*Mz, Mh) per (f, c)
__device__ u64   g_b2 [CC];        // pairs (0.5*bz', bh')
__device__ float g_ph [TT];        // 0.5 * softmax(attention)
__device__ float g_h  [NN * CC];   // fallback h buffer

// --------- K1: deg init + zero y + composite weights + softmax (block 0)
__global__ void k_init_w(const float* __restrict__ Wc_z, const float* __restrict__ bc_z,
                         const float* __restrict__ Wl_z, const float* __restrict__ bl_z,
                         const float* __restrict__ Wc_h, const float* __restrict__ bc_h,
                         const float* __restrict__ Wl_h, const float* __restrict__ bl_h,
                         const float* __restrict__ att) {
    if (blockIdx.x == 0) {
        int t = threadIdx.x;              // 0..511
        int g = t >> 8;                   // 0 = z, 1 = h
        int c = t & (CC - 1);
        const float* Wc = g ? Wc_h : Wc_z;
        const float* bc = g ? bc_h : bc_z;
        const float* Wl = g ? Wl_h : Wl_z;
        const float* bl = g ? bl_h : bl_z;
        float a0 = 0, a1 = 0, a2 = 0, a3 = 0, ab = 0;
        for (int k = 0; k < CC; k++) {
            float wl = Wl[k * CC + c];    // first C rows of [2C, C]
            a0 += Wc[0 * CC + k] * wl;
            a1 += Wc[1 * CC + k] * wl;
            a2 += Wc[2 * CC + k] * wl;
            a3 += Wc[3 * CC + k] * wl;
            ab += bc[k] * wl;
        }
        float s = g ? 1.0f : 0.5f;        // fold tanh half-angle into z weights
        float* M = (float*)g_M2;
        M[(0 * CC + c) * 2 + g] = a0 * s;
        M[(1 * CC + c) * 2 + g] = a1 * s;
        M[(2 * CC + c) * 2 + g] = a2 * s;
        M[(3 * CC + c) * 2 + g] = a3 * s;
        ((float*)g_b2)[c * 2 + g] = (ab + bl[c]) * s;
        if (t == 0) {                     // 0.5 * softmax(attention)
            float m = -1e30f;
            for (int k = 0; k < TT; k++) m = fmaxf(m, att[k]);
            float sum = 0.0f, e[TT];
            for (int k = 0; k < TT; k++) { e[k] = __expf(att[k] - m); sum += e[k]; }
            float inv = 0.5f / sum;
            for (int k = 0; k < TT; k++) g_ph[k] = e[k] * inv;
        }
    } else {
        int i = (blockIdx.x - 1) * blockDim.x + threadIdx.x;
        if (i < NREG * NN) g_deg[i] = 1.0f;            // +1 from self-loop
        if (i < NN * TT)                               // zero message buffer
            reinterpret_cast<float4*>(g_y)[i] = make_float4(0.f, 0.f, 0.f, 0.f);
    }
}

// ------------------------------------------------------------- K2: deg scatter
__global__ void k_deg(RegPtrs rp) {
    int i = blockIdx.x * blockDim.x + threadIdx.x;
    if (i >= NREG * ERN) return;
    int r = i / ERN;
    int e = i - r * ERN;
    int dst = rp.ei[r][ERN + e];
    atomicAdd(&g_deg[r * NN + dst], rp.ew[r][e]);
}

// ------------------- K3: message scatter with vector red: y[dst] += coef*x[src]
__global__ void __launch_bounds__(256) k_msg(const float* __restrict__ x, RegPtrs rp) {
    int i = blockIdx.x * blockDim.x + threadIdx.x;   // one edge
    if (i >= NREG * ERN) return;
    int r = i / ERN;
    int e = i - r * ERN;
    int src = rp.ei[r][e];
    int dst = rp.ei[r][ERN + e];
    float w = rp.ew[r][e];
    float coef = rsqrtf(g_deg[r * NN + src]) * w * rsqrtf(g_deg[r * NN + dst]);
    const float4* xs = reinterpret_cast<const float4*>(x) + src * TT;
    float4* yp = reinterpret_cast<float4*>(g_y + dst * FT);
    float4 v[TT];
#pragma unroll
    for (int ch = 0; ch < TT; ch++) v[ch] = xs[ch];   // batch the gathers (MLP)
#pragma unroll
    for (int ch = 0; ch < TT; ch++)
        red4(yp + ch, coef * v[ch].x, coef * v[ch].y, coef * v[ch].z, coef * v[ch].w);
}

// ------------------- K4: fused self-loop + gates + attention pooling + MLP
// 32 nodes per block. Gate is MUFU-bound, MLP is FFMA-bound -> pipes overlap.
__global__ void __launch_bounds__(256) k_fused(const float* __restrict__ x,
                                               const float* __restrict__ W1,
                                               const float* __restrict__ b1,
                                               const float* __restrict__ W2,
                                               const float* __restrict__ b2,
                                               float* __restrict__ hout,
                                               float* __restrict__ yout) {
    __shared__ __align__(16) char pool[32 * CC * 4];  // 32KB: ysp (12KB) then hs
    __shared__ float w2s[HIDN * OUTN];                // 6 KB
    __shared__ float Ssh[32];
    __shared__ float ph[TT];

    u64*   ysp = reinterpret_cast<u64*>(pool);        // [nn][t*4+f] dup pairs
    float* hs  = reinterpret_cast<float*>(pool);      // [nn][c] relu(h) tile
    float* s1  = hs;                                  // layer-1 acts (aliased)

    int tid = threadIdx.x;
    int node0 = blockIdx.x * 32;

    for (int i = tid; i < HIDN * OUTN; i += 256) w2s[i] = W2[i];
    if (tid < TT) ph[tid] = g_ph[tid];
    if (tid < 32) {                                   // self-loop coefficient S
        int n = node0 + tid;
        float S = 0.0f;
#pragma unroll
        for (int r = 0; r < NREG; r++) {
            float d = rsqrtf(g_deg[r * NN + n]);
            S += d * d;
        }
        Ssh[tid] = S;
    }
    __syncthreads();

    // build y tile: messages + S*x, swizzled to [nn][t][f] duplicated pairs
    for (int i = tid; i < 32 * FT; i += 256) {
        int nn = i / FT, j = i - nn * FT;             // j = f*12 + t
        int f = j / TT, t = j - f * TT;
        float v = g_y[(node0 + nn) * FT + j] + Ssh[nn] * x[(node0 + nn) * FT + j];
        ysp[nn * FT + t * 4 + f] = pack2(v, v);
    }
    __syncthreads();

    // ---- gate: h[nn][c] = sum_t (0.5 p_t)(1 - tanh(az/2)) tanh(ah)
    int c = tid;
    u64 m0 = g_M2[0 * CC + c], m1 = g_M2[1 * CC + c];
    u64 m2 = g_M2[2 * CC + c], m3 = g_M2[3 * CC + c];
    u64 b  = g_b2[c];

    float acc[32];
#pragma unroll
    for (int nn = 0; nn < 32; nn++) {
        float h = 0.0f;
#pragma unroll
        for (int t = 0; t < TT; t++) {
            u64 a = ffma2(ysp[nn * FT + t * 4 + 0], m0, b);
            a = ffma2(ysp[nn * FT + t * 4 + 1], m1, a);
            a = ffma2(ysp[nn * FT + t * 4 + 2], m2, a);
            a = ffma2(ysp[nn * FT + t * 4 + 3], m3, a);
            float azh, ahh;
            unpack2(a, azh, ahh);                     // lo = az/2, hi = ah
            float tz = tanh_fast(azh);
            float th = tanh_fast(ahh);
            h = fmaf(ph[t] * (1.0f - tz), th, h);
        }
        acc[nn] = h;
    }
    // write raw h out (coalesced per nn)
#pragma unroll
    for (int nn = 0; nn < 32; nn++)
        hout[(size_t)(node0 + nn) * CC + c] = acc[nn];

    if (!yout) return;

    __syncthreads();                                  // ysp reads done
#pragma unroll
    for (int nn = 0; nn < 32; nn++)
        hs[nn * CC + c] = fmaxf(acc[nn], 0.0f);
    __syncthreads();

    // ---- MLP layer 1: [32,256] @ [256,128], f32x2 over C pairs
    int g   = tid >> 7;                               // node-group 0/1
    int hid = tid & (HIDN - 1);
    const float* hsg = hs + g * 16 * CC;

    u64 a1[16];
#pragma unroll
    for (int nn = 0; nn < 16; nn++) a1[nn] = 0ull;

#pragma unroll 2
    for (int k4 = 0; k4 < CC; k4 += 4) {
        u64 wp0 = pack2(W1[(k4 + 0) * HIDN + hid], W1[(k4 + 1) * HIDN + hid]);
        u64 wp1 = pack2(W1[(k4 + 2) * HIDN + hid], W1[(k4 + 3) * HIDN + hid]);
#pragma unroll
        for (int nn = 0; nn < 16; nn++) {
            ulonglong2 hv = *reinterpret_cast<const ulonglong2*>(hsg + nn * CC + k4);
            a1[nn] = ffma2(hv.x, wp0, a1[nn]);
            a1[nn] = ffma2(hv.y, wp1, a1[nn]);
        }
    }

    float bias1 = b1[hid];
    float res[16];
#pragma unroll
    for (int nn = 0; nn < 16; nn++) {
        float lo, hi;
        unpack2(a1[nn], lo, hi);
        res[nn] = fmaxf(lo + hi + bias1, 0.0f);
    }
    __syncthreads();                                  // hs reads done before alias
#pragma unroll
    for (int nn = 0; nn < 16; nn++)
        s1[(g * 16 + nn) * HIDN + hid] = res[nn];
    __syncthreads();

    // ---- MLP layer 2: 32 nodes x 12 outputs
    for (int o = tid; o < 32 * OUTN; o += 256) {
        int node = o / OUTN;
        int oo   = o - node * OUTN;
        float a = b2[oo];
#pragma unroll 4
        for (int k = 0; k < HIDN; k++)
            a = fmaf(s1[node * HIDN + k], w2s[k * OUTN + oo], a);
        yout[(node0 + node) * OUTN + oo] = a;
    }
}

// ================================================================== host
extern "C" void kernel_launch(void* const* d_in, const int* in_sizes, int n_in,
                              void* d_out, int out_size) {
    const float* x = (const float*)d_in[0];
    RegPtrs rp;
    for (int r = 0; r < NREG; r++) {
        rp.ei[r] = (const int*)d_in[2 + r];     // IA,KS,KY,OH,WI edge_index
        rp.ew[r] = (const float*)d_in[7 + r];   // matching edge_attr
    }
    const float* Wc_z = (const float*)d_in[12];
    const float* bc_z = (const float*)d_in[13];
    const float* Wl_z = (const float*)d_in[14];
    const float* bl_z = (const float*)d_in[15];
    const float* Wc_h = (const float*)d_in[20];
    const float* bc_h = (const float*)d_in[21];
    const float* Wl_h = (const float*)d_in[22];
    const float* bl_h = (const float*)d_in[23];
    const float* att  = (const float*)d_in[24];
    const float* W1   = (const float*)d_in[25];
    const float* b1   = (const float*)d_in[26];
    const float* W2   = (const float*)d_in[27];
    const float* b2   = (const float*)d_in[28];

    float* out  = (float*)d_out;
    float* ydst = nullptr;
    float* hdst = nullptr;
    if (out_size >= NN * OUTN + NN * CC) { ydst = out; hdst = out + NN * OUTN; }
    else if (out_size >= NN * CC)        { hdst = out; }
    else                                 { ydst = out; }

    float* hbuf = hdst;
    if (!hbuf) {
        void* p = nullptr;
        cudaGetSymbolAddress(&p, g_h);
        hbuf = (float*)p;
    }

    k_init_w<<<1 + (NN * TT + 511) / 512, 512>>>(Wc_z, bc_z, Wl_z, bl_z,
                                                 Wc_h, bc_h, Wl_h, bl_h, att);
    k_deg<<<(NREG * ERN + 255) / 256, 256>>>(rp);
    k_msg<<<(NREG * ERN + 255) / 256, 256>>>(x, rp);
    k_fused<<<NN / 32, 256>>>(x, W1, b1, W2, b2, hbuf, ydst);
}